// round 16
// baseline (speedup 1.0000x reference)
#include <cuda_runtime.h>
#include <cuda_fp16.h>
#include <cstdint>

#define D_   768
#define NH_  12
#define P_   5
#define NL_  54
#define NS_  256
#define B_   128
#define NTL_ 49
#define ML_  (B_*NL_)
#define MS_  (B_*NS_)
#define DD_  ((size_t)768*768)

__device__ float g_local[(size_t)ML_*D_];
__device__ float g_scene[(size_t)MS_*D_];
__device__ float g_lsin [B_*NTL_*32];
__device__ float g_lcos [B_*NTL_*32];
__device__ float g_ssin [NS_*32];
__device__ float g_scos [NS_*32];
__device__ __half g_wt[(size_t)12*20*DD_];
__device__ __half g_lh  [(size_t)ML_*D_];
__device__ __half g_sh  [(size_t)MS_*D_];
__device__ __half g_aoh [(size_t)MS_*D_];
__device__ __half g_hbh [(size_t)ML_*D_];
__device__ __half g_mh  [(size_t)ML_*4*D_];
__device__ __half g_qh  [(size_t)ML_*D_];
__device__ __half g_kvh [(size_t)ML_*2*D_];
__device__ __half g_kvq [(size_t)MS_*3*D_];
__device__ __half g_qkvh[(size_t)ML_*3*D_];

__device__ __forceinline__ uint32_t smem_to_u32(const void* p){
    uint32_t a;
    asm("{ .reg .u64 t; cvta.to.shared.u64 t, %1; cvt.u32.u64 %0, t; }" : "=r"(a) : "l"(p));
    return a;
}
#define SWZ(o) ((o) ^ (((o)>>3)&0x70))
#define CPA16(dst,src) asm volatile("cp.async.cg.shared.global [%0],[%1],16;"::"r"(dst),"l"(src))
#define CPA_COMMIT() asm volatile("cp.async.commit_group;")

__device__ __forceinline__ void ldsm4(uint32_t* r, uint32_t addr){
    asm volatile("ldmatrix.sync.aligned.m8n8.x4.shared.b16 {%0,%1,%2,%3},[%4];"
        : "=r"(r[0]),"=r"(r[1]),"=r"(r[2]),"=r"(r[3]) : "r"(addr));
}
__device__ __forceinline__ void ldsm4t(uint32_t* r, uint32_t addr){
    asm volatile("ldmatrix.sync.aligned.m8n8.x4.trans.shared.b16 {%0,%1,%2,%3},[%4];"
        : "=r"(r[0]),"=r"(r[1]),"=r"(r[2]),"=r"(r[3]) : "r"(addr));
}
__device__ __forceinline__ void mma16816(float* d, const uint32_t* a, const uint32_t* b){
    asm volatile("mma.sync.aligned.m16n8k16.row.col.f32.f16.f16.f32 "
        "{%0,%1,%2,%3},{%4,%5,%6,%7},{%8,%9},{%0,%1,%2,%3};"
        : "+f"(d[0]),"+f"(d[1]),"+f"(d[2]),"+f"(d[3])
        : "r"(a[0]),"r"(a[1]),"r"(a[2]),"r"(a[3]),"r"(b[0]),"r"(b[1]));
}
__device__ __forceinline__ float gelu_f(float x){
    float t = tanhf(0.7978845608028654f*(x + 0.044715f*x*x*x));
    return 0.5f*x*(1.0f+t);
}
__device__ __forceinline__ void cvt2(float2 v, __half* H, size_t idx){
    *reinterpret_cast<__half2*>(H+idx) =
        __halves2half2(__float2half_rn(v.x), __float2half_rn(v.y));
}

// ---- ALL weights: fp32 [K][N] -> fp16 [N][K] in one launch ----
// Wtab order (host): rWq, rWk, rWv, wWq, wWk, wWv, rWo, wWo
// -> offsets: rWq=0 | rWk=1,rWv=2,wWq=3 (contiguous = scene kvq B) | wWk=4,wWv=5 | rWo=6 | wWo=7
__global__ void wsplit_all(const float* p0, const float* p1, const float* p2, const float* p3,
                           const float* p4, const float* p5, const float* p6, const float* p7,
                           const float* qkvW, const float* aWo, const float* mW1, const float* mW2,
                           __half* wt)
{
    const float* Wtab[8] = {p0,p1,p2,p3,p4,p5,p6,p7};
    int t = blockIdx.x, l = blockIdx.y;
    const float* W; size_t off; int K=768, N=768, nx=24;
    if (t < 4608){ int m=t/576; t-=m*576; W=Wtab[m]; off=(size_t)m*DD_; }
    else if (t < 6336){ t-=4608; W=qkvW; off=8*DD_;  N=2304; nx=72; }
    else if (t < 6912){ t-=6336; W=aWo;  off=11*DD_; }
    else if (t < 9216){ t-=6912; W=mW1;  off=12*DD_; N=3072; nx=96; }
    else              { t-=9216; W=mW2;  off=16*DD_; K=3072; }
    int n0=(t%nx)<<5, k0=(t/nx)<<5;
    const int tx = threadIdx.x, ty = threadIdx.y;
    __shared__ float tt[32][33];
    const float* Wl = W + (size_t)l*K*N;
    #pragma unroll
    for (int j=0;j<4;j++) tt[ty+8*j][tx] = Wl[(size_t)(k0+ty+8*j)*N + n0+tx];
    __syncthreads();
    __half* hi = wt + (size_t)l*(20*DD_) + off;
    #pragma unroll
    for (int j=0;j<4;j++)
        hi[(size_t)(n0+ty+8*j)*K + k0+tx] = __float2half_rn(tt[tx][ty+8*j]);
}

__global__ __launch_bounds__(256) void aconv(const float* __restrict__ X, __half* __restrict__ H)
{
    int i = blockIdx.x*256 + threadIdx.x;
    float4 a = reinterpret_cast<const float4*>(X)[i];
    cvt2(make_float2(a.x,a.y), H, (size_t)i*4);
    cvt2(make_float2(a.z,a.w), H, (size_t)i*4+2);
}
__global__ __launch_bounds__(256) void copyf(const float* __restrict__ X, float* __restrict__ Y)
{
    int i = blockIdx.x*256 + threadIdx.x;
    reinterpret_cast<float4*>(Y)[i] = reinterpret_cast<const float4*>(X)[i];
}

// ======== epilogue helper ========
template<int EPI, int SPLIT>
__device__ __forceinline__ void epi_store(float* C, __half* Hs, const float* gate,
        int N, int r0, int col, float* a4)
{
    size_t i0 = (size_t)r0*N + col;
    size_t i1 = i0 + 8*(size_t)N;
    float2 v0 = make_float2(a4[0], a4[1]);
    float2 v1 = make_float2(a4[2], a4[3]);
    if (EPI==1){
        v0.x=gelu_f(v0.x); v0.y=gelu_f(v0.y); v1.x=gelu_f(v1.x); v1.y=gelu_f(v1.y);
    } else if (EPI==2){
        float2 o0 = *reinterpret_cast<float2*>(C+i0);
        float2 o1 = *reinterpret_cast<float2*>(C+i1);
        v0.x+=o0.x; v0.y+=o0.y; v1.x+=o1.x; v1.y+=o1.y;
    } else if (EPI==3){
        float g0 = gate[col], g1 = gate[col+1];
        float2 o0 = *reinterpret_cast<float2*>(C+i0);
        float2 o1 = *reinterpret_cast<float2*>(C+i1);
        v0.x=o0.x+g0*v0.x; v0.y=o0.y+g1*v0.y;
        v1.x=o1.x+g0*v1.x; v1.y=o1.y+g1*v1.y;
    }
    if (SPLIT != 2){
        *reinterpret_cast<float2*>(C+i0) = v0;
        *reinterpret_cast<float2*>(C+i1) = v1;
    }
    if (SPLIT >= 1){ cvt2(v0, Hs, i0); cvt2(v1, Hs, i1); }
}

// ======== GEMM 64x128 (3 CTA/SM, 3-stage 24KB) — used for ALL GEMMs ========
#define STG64 24576
#define SMG64 (3*STG64)
template<int EPI, int SPLIT>
__global__ __launch_bounds__(256,3) void mmagemm64(const __half* __restrict__ Ah,
        const __half* __restrict__ Bh, float* __restrict__ C, __half* __restrict__ Hs,
        const float* __restrict__ gate, int M, int N, int K)
{
    extern __shared__ char smc[];
    const uint32_t sb = smem_to_u32(smc);
    const int tid = threadIdx.x, wid = tid>>5, lane = tid&31;
    const int mw = wid>>2, nw = wid&3;            // 2M x 4N warps, warp tile 32x32
    const int m0 = blockIdx.y<<6, n0 = blockIdx.x<<7;

    float acc[2][4][4];
    #pragma unroll
    for (int i=0;i<2;i++)
        #pragma unroll
        for (int j=0;j<4;j++)
            #pragma unroll
            for (int q=0;q<4;q++) acc[i][j][q]=0.f;

    const int NC = K>>6;
    auto issue = [&](int c){
        const int s = c%3, kc = c<<6;
        const uint32_t sbase = sb + s*STG64;
        #pragma unroll
        for (int it=0; it<2; it++){               // A 64x64 = 8KB
            int u = (it<<8) + tid;
            int r = u>>3, c16 = u&7;
            CPA16(sbase + SWZ((uint32_t)(r*128 + c16*16)),
                  Ah + (size_t)(m0+r)*K + kc + (c16<<3));
        }
        #pragma unroll
        for (int it=0; it<4; it++){               // B 128x64 = 16KB
            int u = (it<<8) + tid;
            int r = u>>3, c16 = u&7;
            CPA16(sbase + 8192 + SWZ((uint32_t)(r*128 + c16*16)),
                  Bh + (size_t)(n0+r)*K + kc + (c16<<3));
        }
        CPA_COMMIT();
    };
    issue(0);
    if (NC>1) issue(1);
    for (int c=0; c<NC; c++){
        if (c+1 < NC) asm volatile("cp.async.wait_group 1;");
        else          asm volatile("cp.async.wait_group 0;");
        __syncthreads();
        if (c+2 < NC) issue(c+2);
        const uint32_t sbase = sb + (c%3)*STG64;
        #pragma unroll
        for (int ks=0; ks<4; ks++){
            uint32_t ah[2][4], bh[2][4];
            #pragma unroll
            for (int ma=0; ma<2; ma++){
                int row = (mw<<5) + (ma<<4) + (lane&15);
                int kb  = (ks<<4) + ((lane>>4)<<3);
                ldsm4(ah[ma], sbase + SWZ((uint32_t)(row*128 + kb*2)));
            }
            #pragma unroll
            for (int nb=0; nb<2; nb++){
                int row = (nw<<5) + (nb<<4) + (lane&7) + ((lane>>4)<<3);
                int kb  = (ks<<4) + (((lane>>3)&1)<<3);
                ldsm4(bh[nb], sbase + 8192 + SWZ((uint32_t)(row*128 + kb*2)));
            }
            #pragma unroll
            for (int nb=0; nb<2; nb++)
                #pragma unroll
                for (int ma=0; ma<2; ma++){
                    mma16816(acc[ma][2*nb],   ah[ma], bh[nb]);
                    mma16816(acc[ma][2*nb+1], ah[ma], bh[nb]+2);
                }
        }
    }
    const int g = lane>>2, t = lane&3;
    #pragma unroll
    for (int ma=0; ma<2; ma++){
        int r0 = m0 + (mw<<5) + (ma<<4) + g;
        #pragma unroll
        for (int na=0; na<4; na++){
            int col = n0 + (nw<<5) + (na<<3) + (t<<1);
            epi_store<EPI,SPLIT>(C, Hs, gate, N, r0, col, acc[ma][na]);
        }
    }
}

// ---- LayerNorm ----
__global__ __launch_bounds__(256) void layernorm_k(const float* __restrict__ X,
        __half* __restrict__ H, const float* __restrict__ g, const float* __restrict__ bb)
{
    __shared__ float red[8], red2[8];
    const int row = blockIdx.x, tid = threadIdx.x, lane = tid&31, wid = tid>>5;
    const float* x = X + (size_t)row*D_;
    float v0=x[tid], v1=x[tid+256], v2=x[tid+512];
    float s = v0+v1+v2;
    #pragma unroll
    for (int o=16;o;o>>=1) s += __shfl_xor_sync(0xffffffffu, s, o);
    if (lane==0) red[wid]=s;
    __syncthreads();
    float mean = (red[0]+red[1]+red[2]+red[3]+red[4]+red[5]+red[6]+red[7])*(1.f/768.f);
    float d0=v0-mean, d1=v1-mean, d2=v2-mean;
    float q = d0*d0+d1*d1+d2*d2;
    #pragma unroll
    for (int o=16;o;o>>=1) q += __shfl_xor_sync(0xffffffffu, q, o);
    if (lane==0) red2[wid]=q;
    __syncthreads();
    float inv = rsqrtf((red2[0]+red2[1]+red2[2]+red2[3]+red2[4]+red2[5]+red2[6]+red2[7])*(1.f/768.f)+1e-6f);
    size_t base = (size_t)row*D_;
    H[base+tid]     = __float2half_rn(d0*inv*g[tid]     + bb[tid]);
    H[base+tid+256] = __float2half_rn(d1*inv*g[tid+256] + bb[tid+256]);
    H[base+tid+512] = __float2half_rn(d2*inv*g[tid+512] + bb[tid+512]);
}

// ---- RoPE tables (merged) ----
__global__ void rope_pre(const float* __restrict__ centers, const float* __restrict__ scales){
    int t = blockIdx.x, b = blockIdx.y, j = threadIdx.x;
    float f = expf(-4.605170185988091f*(float)(j&15)*(1.f/16.f));
    if (b < B_){
        float gy=(t/7+0.5f)*(2.f/7.f)-1.f, gx=(t%7+0.5f)*(2.f/7.f)-1.f;
        float sc=scales[b];
        float pos=(j<16)?(centers[2*b]+sc*gy):(centers[2*b+1]+sc*gx);
        if (t < NTL_){
            float a=pos*f;
            int idx=(b*NTL_+t)*32+j;
            g_lsin[idx]=sinf(a); g_lcos[idx]=cosf(a);
        }
    } else {
        float gy=(t/16+0.5f)*(2.f/16.f)-1.f, gx=(t%16+0.5f)*(2.f/16.f)-1.f;
        float pos=(j<16)?gy:gx;
        float a=pos*f;
        g_ssin[t*32+j]=sinf(a); g_scos[t*32+j]=cosf(a);
    }
}

// ---- attention ----
#define AQ_OFF  0
#define AKV_OFF 8192
#define AS_OFF  16384
#define AP_OFF  81920
#define SMATT   114688
__global__ __launch_bounds__(256,2) void attn3(
    const __half* __restrict__ Q, const __half* __restrict__ K, const __half* __restrict__ V,
    __half* __restrict__ Oh, int Nq, int Nk, int qs, int ks,
    const float* __restrict__ qS, const float* __restrict__ qC, int qpre, int qbi,
    const float* __restrict__ kS, const float* __restrict__ kC, int kpre, int kbi)
{
    extern __shared__ char smc[];
    const uint32_t sb = smem_to_u32(smc);
    float* Sm = reinterpret_cast<float*>(smc + AS_OFF);
    const int q0 = blockIdx.x<<6, h = blockIdx.y, b = blockIdx.z;
    const int tid = threadIdx.x, wid = tid>>5, lane = tid&31;
    const int mw = wid>>1, nw = wid&1;

    {
        int r = tid>>2, pj = (tid&3)<<3;
        int t = q0 + r;
        uint4 lo = make_uint4(0,0,0,0), hi = make_uint4(0,0,0,0);
        if (t < Nq){
            const __half* qp = Q + (size_t)(b*Nq+t)*qs + h*64;
            lo = *reinterpret_cast<const uint4*>(qp + pj);
            hi = *reinterpret_cast<const uint4*>(qp + pj + 32);
            if (t >= qpre){
                int so = (qbi ? t*32 : (b*NTL_ + (t-qpre))*32) + pj;
                __half2* l2 = reinterpret_cast<__half2*>(&lo);
                __half2* h2 = reinterpret_cast<__half2*>(&hi);
                #pragma unroll
                for (int jj=0;jj<4;jj++){
                    float2 x1 = __half22float2(l2[jj]);
                    float2 x2 = __half22float2(h2[jj]);
                    float s0=qS[so+2*jj], c0=qC[so+2*jj];
                    float s1=qS[so+2*jj+1], c1=qC[so+2*jj+1];
                    l2[jj] = __floats2half2_rn(x1.x*c0-x2.x*s0, x1.y*c1-x2.y*s1);
                    h2[jj] = __floats2half2_rn(x2.x*c0+x1.x*s0, x2.y*c1+x1.y*s1);
                }
            }
        }
        *reinterpret_cast<uint4*>(smc + AQ_OFF + SWZ(r*128 + pj*2)) = lo;
        *reinterpret_cast<uint4*>(smc + AQ_OFF + SWZ(r*128 + pj*2 + 64)) = hi;
    }

    const int NC = (Nk + 63) >> 6;
    for (int c=0;c<NC;c++){
        int c0 = c<<6;
        __syncthreads();
        {
            int r = tid>>2, pj = (tid&3)<<3;
            int t = c0 + r;
            uint4 lo = make_uint4(0,0,0,0), hi = make_uint4(0,0,0,0);
            if (t < Nk){
                const __half* kp = K + (size_t)(b*Nk+t)*ks + h*64;
                lo = *reinterpret_cast<const uint4*>(kp + pj);
                hi = *reinterpret_cast<const uint4*>(kp + pj + 32);
                if (t >= kpre){
                    int so = (kbi ? t*32 : (b*NTL_ + (t-kpre))*32) + pj;
                    __half2* l2 = reinterpret_cast<__half2*>(&lo);
                    __half2* h2 = reinterpret_cast<__half2*>(&hi);
                    #pragma unroll
                    for (int jj=0;jj<4;jj++){
                        float2 x1 = __half22float2(l2[jj]);
                        float2 x2 = __half22float2(h2[jj]);
                        float s0=kS[so+2*jj], c0f=kC[so+2*jj];
                        float s1=kS[so+2*jj+1], c1f=kC[so+2*jj+1];
                        l2[jj] = __floats2half2_rn(x1.x*c0f-x2.x*s0, x1.y*c1f-x2.y*s1);
                        h2[jj] = __floats2half2_rn(x2.x*c0f+x1.x*s0, x2.y*c1f+x1.y*s1);
                    }
                }
            }
            *reinterpret_cast<uint4*>(smc + AKV_OFF + SWZ(r*128 + pj*2)) = lo;
            *reinterpret_cast<uint4*>(smc + AKV_OFF + SWZ(r*128 + pj*2 + 64)) = hi;
        }
        __syncthreads();
        float acc[4][4] = {};
        #pragma unroll
        for (int ks_=0;ks_<4;ks_++){
            uint32_t af[4];
            ldsm4(af, sb + AQ_OFF + SWZ(((mw<<4)+(lane&15))*128 + ((ks_<<4)+((lane>>4)<<3))*2));
            #pragma unroll
            for (int np=0;np<2;np++){
                uint32_t bf[4];
                int krow = (nw<<5)+(np<<4)+(lane&7)+((lane>>4)<<3);
                ldsm4(bf, sb + AKV_OFF + SWZ(krow*128 + ((ks_<<4)+(((lane>>3)&1)<<3))*2));
                mma16816(acc[2*np],   af, bf);
                mma16816(acc[2*np+1], af, bf+2);
            }
        }
        int g = lane>>2, tq = lane&3;
        #pragma unroll
        for (int j=0;j<4;j++){
            int col = c0 + (nw<<5) + ((j>>1)<<4) + ((j&1)<<3) + (tq<<1);
            int r0 = (mw<<4)+g;
            float* s0 = Sm + r0*256 + col;
            s0[0]=acc[j][0]*0.125f; s0[1]=acc[j][1]*0.125f;
            float* s1 = s0 + 8*256;
            s1[0]=acc[j][2]*0.125f; s1[1]=acc[j][3]*0.125f;
        }
    }
    __syncthreads();

    {
        int Nkp = NC<<6;
        for (int rr=0;rr<8;rr++){
            int row = (wid<<3)+rr;
            float* Srow = Sm + row*256;
            float m = -1e30f;
            for (int i=lane;i<Nk;i+=32) m = fmaxf(m, Srow[i]);
            #pragma unroll
            for (int o=16;o>0;o>>=1) m = fmaxf(m, __shfl_xor_sync(0xffffffffu, m, o));
            float sum = 0.f;
            for (int i=lane;i<Nk;i+=32){ float e = expf(Srow[i]-m); Srow[i]=e; sum+=e; }
            #pragma unroll
            for (int o=16;o>0;o>>=1) sum += __shfl_xor_sync(0xffffffffu, sum, o);
            float inv = 1.f/sum;
            for (int i=lane;i<Nkp;i+=32){
                __half p = (i<Nk) ? __float2half_rn(Srow[i]*inv) : __float2half_rn(0.f);
                *reinterpret_cast<__half*>(smc + AP_OFF + row*512 +
                    ((((i>>3)^(row&7)))<<4) + ((i&7)<<1)) = p;
            }
        }
    }

    float oacc[4][4] = {};
    for (int c=0;c<NC;c++){
        int c0 = c<<6;
        __syncthreads();
        {
            int r = tid>>2, pj = (tid&3)<<3;
            int t = c0 + r;
            uint4 lo = make_uint4(0,0,0,0), hi = make_uint4(0,0,0,0);
            if (t < Nk){
                const __half* vp = V + (size_t)(b*Nk+t)*ks + h*64;
                lo = *reinterpret_cast<const uint4*>(vp + pj);
                hi = *reinterpret_cast<const uint4*>(vp + pj + 32);
            }
            *reinterpret_cast<uint4*>(smc + AKV_OFF + SWZ(r*128 + pj*2)) = lo;
            *reinterpret_cast<uint4*>(smc + AKV_OFF + SWZ(r*128 + pj*2 + 64)) = hi;
        }
        __syncthreads();
        #pragma unroll
        for (int ks_=0;ks_<4;ks_++){
            uint32_t af[4];
            int prow = (mw<<4)+(lane&15);
            int pcol = c0 + (ks_<<4) + ((lane>>4)<<3);
            ldsm4(af, sb + AP_OFF + prow*512 + (((pcol>>3)^(prow&7))<<4));
            #pragma unroll
            for (int np=0;np<2;np++){
                uint32_t bf[4];
                int vrow = (ks_<<4) + (((lane>>3)&1)<<3) + (lane&7);
                int vcol = (nw<<5) + (np<<4) + ((lane>>4)<<3);
                ldsm4t(bf, sb + AKV_OFF + SWZ(vrow*128 + vcol*2));
                mma16816(oacc[2*np],   af, bf);
                mma16816(oacc[2*np+1], af, bf+2);
            }
        }
    }
    {
        int g = lane>>2, tq = lane&3;
        #pragma unroll
        for (int j=0;j<4;j++){
            int col = (nw<<5)+((j>>1)<<4)+((j&1)<<3)+(tq<<1);
            int r0 = (mw<<4)+g;
            if (q0+r0 < Nq){
                size_t i0 = (size_t)(b*Nq + q0 + r0)*D_ + h*64 + col;
                *reinterpret_cast<__half2*>(Oh+i0) = __floats2half2_rn(oacc[j][0], oacc[j][1]);
            }
            if (q0+r0+8 < Nq){
                size_t i1 = (size_t)(b*Nq + q0 + r0 + 8)*D_ + h*64 + col;
                *reinterpret_cast<__half2*>(Oh+i1) = __floats2half2_rn(oacc[j][2], oacc[j][3]);
            }
        }
    }
}

__global__ void bcast_scene(const float* __restrict__ st){
    int off = blockIdx.x*256 + threadIdx.x;
    float v = st[off];
    size_t i = (size_t)blockIdx.y*(NS_*D_) + off;
    g_scene[i] = v;
    g_sh[i] = __float2half_rn(v);
}

extern "C" void kernel_launch(void* const* d_in, const int* in_sizes, int n_in,
                              void* d_out, int out_size)
{
    (void)in_sizes; (void)n_in; (void)out_size;
    const float *in_local=(const float*)d_in[0], *in_centers=(const float*)d_in[1],
        *in_scales=(const float*)d_in[2], *in_scene=(const float*)d_in[3],
        *rgate=(const float*)d_in[4], *wgate=(const float*)d_in[5],
        *rWq=(const float*)d_in[6], *rWk=(const float*)d_in[7], *rWv=(const float*)d_in[8],
        *rWo=(const float*)d_in[9], *wWq=(const float*)d_in[10], *wWk=(const float*)d_in[11],
        *wWv=(const float*)d_in[12], *wWo=(const float*)d_in[13],
        *ln1g=(const float*)d_in[14], *ln1b=(const float*)d_in[15],
        *qkvW=(const float*)d_in[16], *aWo=(const float*)d_in[17],
        *ln2g=(const float*)d_in[18], *ln2b=(const float*)d_in[19],
        *mW1=(const float*)d_in[20], *mW2=(const float*)d_in[21];

    float *local,*scene,*lsin,*lcos,*ssin,*scos;
    __half *wt,*lh,*sh,*aoh,*hbh,*mh,*qh,*kvh,*kvq,*qkvh;
    cudaGetSymbolAddress((void**)&local,g_local); cudaGetSymbolAddress((void**)&scene,g_scene);
    cudaGetSymbolAddress((void**)&lsin,g_lsin); cudaGetSymbolAddress((void**)&lcos,g_lcos);
    cudaGetSymbolAddress((void**)&ssin,g_ssin); cudaGetSymbolAddress((void**)&scos,g_scos);
    cudaGetSymbolAddress((void**)&wt,g_wt);
    cudaGetSymbolAddress((void**)&lh,g_lh);   cudaGetSymbolAddress((void**)&sh,g_sh);
    cudaGetSymbolAddress((void**)&aoh,g_aoh); cudaGetSymbolAddress((void**)&hbh,g_hbh);
    cudaGetSymbolAddress((void**)&mh,g_mh);
    cudaGetSymbolAddress((void**)&qh,g_qh);   cudaGetSymbolAddress((void**)&kvh,g_kvh);
    cudaGetSymbolAddress((void**)&kvq,g_kvq); cudaGetSymbolAddress((void**)&qkvh,g_qkvh);

    cudaFuncSetAttribute(mmagemm64<0,2>, cudaFuncAttributeMaxDynamicSharedMemorySize, SMG64);
    cudaFuncSetAttribute(mmagemm64<1,2>, cudaFuncAttributeMaxDynamicSharedMemorySize, SMG64);
    cudaFuncSetAttribute(mmagemm64<2,0>, cudaFuncAttributeMaxDynamicSharedMemorySize, SMG64);
    cudaFuncSetAttribute(mmagemm64<2,1>, cudaFuncAttributeMaxDynamicSharedMemorySize, SMG64);
    cudaFuncSetAttribute(mmagemm64<3,0>, cudaFuncAttributeMaxDynamicSharedMemorySize, SMG64);
    cudaFuncSetAttribute(mmagemm64<3,1>, cudaFuncAttributeMaxDynamicSharedMemorySize, SMG64);
    cudaFuncSetAttribute(attn3, cudaFuncAttributeMaxDynamicSharedMemorySize, SMATT);

    const size_t LS = 20*DD_;
    // weight order: rWq, rWk, rWv, wWq, wWk, wWv, rWo, wWo
    wsplit_all<<<dim3(11520,12), dim3(32,8)>>>(rWq,rWk,rWv,wWq,wWk,wWv,rWo,wWo,
                                               qkvW,aWo,mW1,mW2, wt);
    aconv<<<ML_*D_/1024,256>>>(in_local, lh);
    bcast_scene<<<dim3(NS_*D_/256, B_),256>>>(in_scene);

    for (int i=0;i<12;i++){
        const __half* wb = wt + (size_t)i*LS;
        // ---- scene-side merged K/V/Qw projection: N=2304 from sh ----
        mmagemm64<0,2><<<dim3(18,512), 256, SMG64>>>(sh, wb+1*DD_, nullptr, kvq, nullptr, MS_, 2304, 768);
        // ---- local read-Q ----
        mmagemm64<0,2><<<dim3(6,108),  256, SMG64>>>(lh, wb+0*DD_, nullptr, qh, nullptr, ML_, 768, 768);
        if (i==0){
            rope_pre<<<dim3(NS_,B_+1),32>>>(in_centers, in_scales);
            copyf<<<ML_*D_/1024,256>>>(in_local, local);
        }
        attn3<<<dim3(1,NH_,B_),256,SMATT>>>(qh, kvq, kvq+768, aoh, NL_, NS_, 768, 2304,
                                            lsin,lcos,P_,0, ssin,scos,0,1);
        mmagemm64<3,0><<<dim3(6,108),  256, SMG64>>>(aoh, wb+6*DD_, local, nullptr, rgate+(size_t)i*D_, ML_, 768, 768);
        // ---- ViT block ----
        layernorm_k<<<ML_,256>>>(local, hbh, ln1g+(size_t)i*D_, ln1b+(size_t)i*D_);
        mmagemm64<0,2><<<dim3(18,108), 256, SMG64>>>(hbh, wb+8*DD_, nullptr, qkvh, nullptr, ML_, 2304, 768);
        attn3<<<dim3(1,NH_,B_),256,SMATT>>>(qkvh, qkvh+768, qkvh+1536, aoh, NL_, NL_, 2304, 2304,
                                            lsin,lcos,P_,0, lsin,lcos,P_,0);
        mmagemm64<2,0><<<dim3(6,108),  256, SMG64>>>(aoh, wb+11*DD_, local, nullptr, nullptr, ML_, 768, 768);
        layernorm_k<<<ML_,256>>>(local, hbh, ln2g+(size_t)i*D_, ln2b+(size_t)i*D_);
        mmagemm64<1,2><<<dim3(24,108), 256, SMG64>>>(hbh, wb+12*DD_, nullptr, mh, nullptr, ML_, 3072, 768);
        mmagemm64<2,1><<<dim3(6,108),  256, SMG64>>>(mh, wb+16*DD_, local, lh, nullptr, ML_, 768, 3072);
        // ---- local write-KV ----
        mmagemm64<0,2><<<dim3(12,108), 256, SMG64>>>(lh, wb+4*DD_, nullptr, kvh, nullptr, ML_, 1536, 768);
        attn3<<<dim3(4,NH_,B_),256,SMATT>>>(kvq+1536, kvh, kvh+768, aoh, NS_, NL_, 2304, 1536,
                                            ssin,scos,0,1, lsin,lcos,P_,0);
        mmagemm64<3,1><<<dim3(6,512),  256, SMG64>>>(aoh, wb+7*DD_, scene, sh, wgate+(size_t)i*D_, MS_, 768, 768);
    }

    cudaMemcpyAsync(d_out, local, sizeof(float)*(size_t)ML_*D_, cudaMemcpyDeviceToDevice);
    cudaMemcpyAsync((float*)d_out + (size_t)ML_*D_, scene, sizeof(float)*(size_t)MS_*D_,
                    cudaMemcpyDeviceToDevice);
}

// round 17
// speedup vs baseline: 1.0619x; 1.0619x over previous
#include <cuda_runtime.h>
#include <cuda_fp16.h>
#include <cstdint>

#define D_   768
#define NH_  12
#define P_   5
#define NL_  54
#define NS_  256
#define B_   128
#define NTL_ 49
#define ML_  (B_*NL_)
#define MS_  (B_*NS_)
#define DD_  ((size_t)768*768)

__device__ float g_local[(size_t)ML_*D_];
__device__ float g_scene[(size_t)MS_*D_];
__device__ float g_lsin [B_*NTL_*32];
__device__ float g_lcos [B_*NTL_*32];
__device__ float g_ssin [NS_*32];
__device__ float g_scos [NS_*32];
__device__ __half g_wt[(size_t)12*20*DD_];
__device__ __half g_lh  [(size_t)ML_*D_];
__device__ __half g_sh  [(size_t)MS_*D_];
__device__ __half g_aoh [(size_t)MS_*D_];
__device__ __half g_hbh [(size_t)ML_*D_];
__device__ __half g_mh  [(size_t)ML_*4*D_];
__device__ __half g_qh  [(size_t)MS_*D_];
__device__ __half g_kvh [(size_t)MS_*2*D_];
__device__ __half g_qkvh[(size_t)ML_*3*D_];

__device__ __forceinline__ uint32_t smem_to_u32(const void* p){
    uint32_t a;
    asm("{ .reg .u64 t; cvta.to.shared.u64 t, %1; cvt.u32.u64 %0, t; }" : "=r"(a) : "l"(p));
    return a;
}
#define SWZ(o) ((o) ^ (((o)>>3)&0x70))
#define CPA16(dst,src) asm volatile("cp.async.cg.shared.global [%0],[%1],16;"::"r"(dst),"l"(src))
#define CPA16Z(dst,src,ss) asm volatile("cp.async.cg.shared.global [%0],[%1],16,%2;"::"r"(dst),"l"(src),"r"(ss))
#define CPA_COMMIT() asm volatile("cp.async.commit_group;")

__device__ __forceinline__ void ldsm4(uint32_t* r, uint32_t addr){
    asm volatile("ldmatrix.sync.aligned.m8n8.x4.shared.b16 {%0,%1,%2,%3},[%4];"
        : "=r"(r[0]),"=r"(r[1]),"=r"(r[2]),"=r"(r[3]) : "r"(addr));
}
__device__ __forceinline__ void ldsm4t(uint32_t* r, uint32_t addr){
    asm volatile("ldmatrix.sync.aligned.m8n8.x4.trans.shared.b16 {%0,%1,%2,%3},[%4];"
        : "=r"(r[0]),"=r"(r[1]),"=r"(r[2]),"=r"(r[3]) : "r"(addr));
}
__device__ __forceinline__ void mma16816(float* d, const uint32_t* a, const uint32_t* b){
    asm volatile("mma.sync.aligned.m16n8k16.row.col.f32.f16.f16.f32 "
        "{%0,%1,%2,%3},{%4,%5,%6,%7},{%8,%9},{%0,%1,%2,%3};"
        : "+f"(d[0]),"+f"(d[1]),"+f"(d[2]),"+f"(d[3])
        : "r"(a[0]),"r"(a[1]),"r"(a[2]),"r"(a[3]),"r"(b[0]),"r"(b[1]));
}
__device__ __forceinline__ float gelu_f(float x){
    float t = tanhf(0.7978845608028654f*(x + 0.044715f*x*x*x));
    return 0.5f*x*(1.0f+t);
}
__device__ __forceinline__ void cvt2(float2 v, __half* H, size_t idx){
    *reinterpret_cast<__half2*>(H+idx) =
        __halves2half2(__float2half_rn(v.x), __float2half_rn(v.y));
}

// ---- ALL weights: fp32 [K][N] -> fp16 [N][K]; order rWq,rWk,rWv,rWo,wWq,wWk,wWv,wWo ----
__global__ void wsplit_all(const float* p0, const float* p1, const float* p2, const float* p3,
                           const float* p4, const float* p5, const float* p6, const float* p7,
                           const float* qkvW, const float* aWo, const float* mW1, const float* mW2,
                           __half* wt)
{
    const float* Wtab[8] = {p0,p1,p2,p3,p4,p5,p6,p7};
    int t = blockIdx.x, l = blockIdx.y;
    const float* W; size_t off; int K=768, N=768, nx=24;
    if (t < 4608){ int m=t/576; t-=m*576; W=Wtab[m]; off=(size_t)m*DD_; }
    else if (t < 6336){ t-=4608; W=qkvW; off=8*DD_;  N=2304; nx=72; }
    else if (t < 6912){ t-=6336; W=aWo;  off=11*DD_; }
    else if (t < 9216){ t-=6912; W=mW1;  off=12*DD_; N=3072; nx=96; }
    else              { t-=9216; W=mW2;  off=16*DD_; K=3072; }
    int n0=(t%nx)<<5, k0=(t/nx)<<5;
    const int tx = threadIdx.x, ty = threadIdx.y;
    __shared__ float tt[32][33];
    const float* Wl = W + (size_t)l*K*N;
    #pragma unroll
    for (int j=0;j<4;j++) tt[ty+8*j][tx] = Wl[(size_t)(k0+ty+8*j)*N + n0+tx];
    __syncthreads();
    __half* hi = wt + (size_t)l*(20*DD_) + off;
    #pragma unroll
    for (int j=0;j<4;j++)
        hi[(size_t)(n0+ty+8*j)*K + k0+tx] = __float2half_rn(tt[tx][ty+8*j]);
}

__global__ __launch_bounds__(256) void aconv(const float* __restrict__ X, __half* __restrict__ H)
{
    int i = blockIdx.x*256 + threadIdx.x;
    float4 a = reinterpret_cast<const float4*>(X)[i];
    cvt2(make_float2(a.x,a.y), H, (size_t)i*4);
    cvt2(make_float2(a.z,a.w), H, (size_t)i*4+2);
}
__global__ __launch_bounds__(256) void copyf(const float* __restrict__ X, float* __restrict__ Y)
{
    int i = blockIdx.x*256 + threadIdx.x;
    reinterpret_cast<float4*>(Y)[i] = reinterpret_cast<const float4*>(X)[i];
}

// ======== epilogue helper ========
template<int EPI, int SPLIT>
__device__ __forceinline__ void epi_store(float* C, __half* Hs, const float* gate,
        int N, int r0, int col, float* a4)
{
    size_t i0 = (size_t)r0*N + col;
    size_t i1 = i0 + 8*(size_t)N;
    float2 v0 = make_float2(a4[0], a4[1]);
    float2 v1 = make_float2(a4[2], a4[3]);
    if (EPI==1){
        v0.x=gelu_f(v0.x); v0.y=gelu_f(v0.y); v1.x=gelu_f(v1.x); v1.y=gelu_f(v1.y);
    } else if (EPI==2){
        float2 o0 = *reinterpret_cast<float2*>(C+i0);
        float2 o1 = *reinterpret_cast<float2*>(C+i1);
        v0.x+=o0.x; v0.y+=o0.y; v1.x+=o1.x; v1.y+=o1.y;
    } else if (EPI==3){
        float g0 = gate[col], g1 = gate[col+1];
        float2 o0 = *reinterpret_cast<float2*>(C+i0);
        float2 o1 = *reinterpret_cast<float2*>(C+i1);
        v0.x=o0.x+g0*v0.x; v0.y=o0.y+g1*v0.y;
        v1.x=o1.x+g0*v1.x; v1.y=o1.y+g1*v1.y;
    }
    if (SPLIT != 2){
        *reinterpret_cast<float2*>(C+i0) = v0;
        *reinterpret_cast<float2*>(C+i1) = v1;
    }
    if (SPLIT >= 1){ cvt2(v0, Hs, i0); cvt2(v1, Hs, i1); }
}

// ======== GEMM 128x128 (2 CTA/SM, 3-stage 32KB) ========
#define STAGE_ 32768
#define SMEMG (3*STAGE_)
template<int EPI, int SPLIT>
__device__ __forceinline__ void gemm_body(const __half* __restrict__ Ah,
        const __half* __restrict__ Bh, float* __restrict__ C, __half* __restrict__ Hs,
        const float* __restrict__ gate, int N, int K, int m0, int n0, char* smc)
{
    const uint32_t sb = smem_to_u32(smc);
    const int tid = threadIdx.x, wid = tid>>5, lane = tid&31;
    const int mw = wid>>1, nw = wid&1;

    float acc[2][8][4];
    #pragma unroll
    for (int i=0;i<2;i++)
        #pragma unroll
        for (int j=0;j<8;j++)
            #pragma unroll
            for (int q=0;q<4;q++) acc[i][j][q]=0.f;

    const int NC = K>>6;
    auto issue = [&](int c){
        const int s = c%3, kc = c<<6;
        const uint32_t sbase = sb + s*STAGE_;
        #pragma unroll
        for (int it=0; it<4; it++){
            int u = (it<<8) + tid;
            int r = u>>3, c16 = u&7;
            uint32_t dst = sbase + SWZ((uint32_t)(r*128 + c16*16));
            CPA16(dst,         Ah + (size_t)(m0+r)*K + kc + (c16<<3));
            CPA16(dst + 16384, Bh + (size_t)(n0+r)*K + kc + (c16<<3));
        }
        CPA_COMMIT();
    };
    issue(0);
    if (NC>1) issue(1);
    for (int c=0; c<NC; c++){
        if (c+1 < NC) asm volatile("cp.async.wait_group 1;");
        else          asm volatile("cp.async.wait_group 0;");
        __syncthreads();
        if (c+2 < NC) issue(c+2);
        const uint32_t sbase = sb + (c%3)*STAGE_;
        #pragma unroll
        for (int ks=0; ks<4; ks++){
            uint32_t ah[2][4];
            #pragma unroll
            for (int ma=0; ma<2; ma++){
                int row = (mw<<5) + (ma<<4) + (lane&15);
                int kb  = (ks<<4) + ((lane>>4)<<3);
                ldsm4(ah[ma], sbase + SWZ((uint32_t)(row*128 + kb*2)));
            }
            #pragma unroll
            for (int np=0; np<4; np++){
                uint32_t bh[4];
                int row = (nw<<6) + (np<<4) + (lane&7) + ((lane>>4)<<3);
                int kb  = (ks<<4) + (((lane>>3)&1)<<3);
                ldsm4(bh, sbase + 16384 + SWZ((uint32_t)(row*128 + kb*2)));
                #pragma unroll
                for (int ma=0; ma<2; ma++) mma16816(acc[ma][2*np],   ah[ma], bh);
                #pragma unroll
                for (int ma=0; ma<2; ma++) mma16816(acc[ma][2*np+1], ah[ma], bh+2);
            }
        }
    }
    const int g = lane>>2, t = lane&3;
    #pragma unroll
    for (int ma=0; ma<2; ma++){
        int r0 = m0 + (mw<<5) + (ma<<4) + g;
        #pragma unroll
        for (int na=0; na<8; na++){
            int col = n0 + (nw<<6) + (na<<3) + (t<<1);
            epi_store<EPI,SPLIT>(C, Hs, gate, N, r0, col, acc[ma][na]);
        }
    }
}

template<int EPI, int SPLIT>
__global__ __launch_bounds__(256,2) void mmagemm(const __half* __restrict__ Ah,
        const __half* __restrict__ Bh, float* __restrict__ C, __half* __restrict__ Hs,
        const float* __restrict__ gate, int M, int N, int K)
{
    extern __shared__ char smc[];
    gemm_body<EPI,SPLIT>(Ah, Bh, C, Hs, gate, N, K, blockIdx.y<<7, blockIdx.x<<7, smc);
}

__global__ __launch_bounds__(256,2) void mmagemm_pair(
        const __half* __restrict__ A0, const __half* __restrict__ B0, __half* __restrict__ H0,
        int N0, int ntx0, int T0,
        const __half* __restrict__ A1, const __half* __restrict__ B1, __half* __restrict__ H1,
        int N1, int ntx1)
{
    extern __shared__ char smc[];
    int t = blockIdx.x;
    if (t < T0)
        gemm_body<0,2>(A0, B0, nullptr, H0, nullptr, N0, 768, (t/ntx0)<<7, (t%ntx0)<<7, smc);
    else {
        t -= T0;
        gemm_body<0,2>(A1, B1, nullptr, H1, nullptr, N1, 768, (t/ntx1)<<7, (t%ntx1)<<7, smc);
    }
}

// ======== GEMM 64x128 (3 CTA/SM, 3-stage 24KB) for M=6912 ========
#define STG64 24576
#define SMG64 (3*STG64)
template<int EPI, int SPLIT>
__global__ __launch_bounds__(256,3) void mmagemm64(const __half* __restrict__ Ah,
        const __half* __restrict__ Bh, float* __restrict__ C, __half* __restrict__ Hs,
        const float* __restrict__ gate, int M, int N, int K)
{
    extern __shared__ char smc[];
    const uint32_t sb = smem_to_u32(smc);
    const int tid = threadIdx.x, wid = tid>>5, lane = tid&31;
    const int mw = wid>>2, nw = wid&3;
    const int m0 = blockIdx.y<<6, n0 = blockIdx.x<<7;

    float acc[2][4][4];
    #pragma unroll
    for (int i=0;i<2;i++)
        #pragma unroll
        for (int j=0;j<4;j++)
            #pragma unroll
            for (int q=0;q<4;q++) acc[i][j][q]=0.f;

    const int NC = K>>6;
    auto issue = [&](int c){
        const int s = c%3, kc = c<<6;
        const uint32_t sbase = sb + s*STG64;
        #pragma unroll
        for (int it=0; it<2; it++){
            int u = (it<<8) + tid;
            int r = u>>3, c16 = u&7;
            CPA16(sbase + SWZ((uint32_t)(r*128 + c16*16)),
                  Ah + (size_t)(m0+r)*K + kc + (c16<<3));
        }
        #pragma unroll
        for (int it=0; it<4; it++){
            int u = (it<<8) + tid;
            int r = u>>3, c16 = u&7;
            CPA16(sbase + 8192 + SWZ((uint32_t)(r*128 + c16*16)),
                  Bh + (size_t)(n0+r)*K + kc + (c16<<3));
        }
        CPA_COMMIT();
    };
    issue(0);
    if (NC>1) issue(1);
    for (int c=0; c<NC; c++){
        if (c+1 < NC) asm volatile("cp.async.wait_group 1;");
        else          asm volatile("cp.async.wait_group 0;");
        __syncthreads();
        if (c+2 < NC) issue(c+2);
        const uint32_t sbase = sb + (c%3)*STG64;
        #pragma unroll
        for (int ks=0; ks<4; ks++){
            uint32_t ah[2][4], bh[2][4];
            #pragma unroll
            for (int ma=0; ma<2; ma++){
                int row = (mw<<5) + (ma<<4) + (lane&15);
                int kb  = (ks<<4) + ((lane>>4)<<3);
                ldsm4(ah[ma], sbase + SWZ((uint32_t)(row*128 + kb*2)));
            }
            #pragma unroll
            for (int nb=0; nb<2; nb++){
                int row = (nw<<5) + (nb<<4) + (lane&7) + ((lane>>4)<<3);
                int kb  = (ks<<4) + (((lane>>3)&1)<<3);
                ldsm4(bh[nb], sbase + 8192 + SWZ((uint32_t)(row*128 + kb*2)));
            }
            #pragma unroll
            for (int nb=0; nb<2; nb++)
                #pragma unroll
                for (int ma=0; ma<2; ma++){
                    mma16816(acc[ma][2*nb],   ah[ma], bh[nb]);
                    mma16816(acc[ma][2*nb+1], ah[ma], bh[nb]+2);
                }
        }
    }
    const int g = lane>>2, t = lane&3;
    #pragma unroll
    for (int ma=0; ma<2; ma++){
        int r0 = m0 + (mw<<5) + (ma<<4) + g;
        #pragma unroll
        for (int na=0; na<4; na++){
            int col = n0 + (nw<<5) + (na<<3) + (t<<1);
            epi_store<EPI,SPLIT>(C, Hs, gate, N, r0, col, acc[ma][na]);
        }
    }
}

// ---- LayerNorm ----
__global__ __launch_bounds__(256) void layernorm_k(const float* __restrict__ X,
        __half* __restrict__ H, const float* __restrict__ g, const float* __restrict__ bb)
{
    __shared__ float red[8], red2[8];
    const int row = blockIdx.x, tid = threadIdx.x, lane = tid&31, wid = tid>>5;
    const float* x = X + (size_t)row*D_;
    float v0=x[tid], v1=x[tid+256], v2=x[tid+512];
    float s = v0+v1+v2;
    #pragma unroll
    for (int o=16;o;o>>=1) s += __shfl_xor_sync(0xffffffffu, s, o);
    if (lane==0) red[wid]=s;
    __syncthreads();
    float mean = (red[0]+red[1]+red[2]+red[3]+red[4]+red[5]+red[6]+red[7])*(1.f/768.f);
    float d0=v0-mean, d1=v1-mean, d2=v2-mean;
    float q = d0*d0+d1*d1+d2*d2;
    #pragma unroll
    for (int o=16;o;o>>=1) q += __shfl_xor_sync(0xffffffffu, q, o);
    if (lane==0) red2[wid]=q;
    __syncthreads();
    float inv = rsqrtf((red2[0]+red2[1]+red2[2]+red2[3]+red2[4]+red2[5]+red2[6]+red2[7])*(1.f/768.f)+1e-6f);
    size_t base = (size_t)row*D_;
    H[base+tid]     = __float2half_rn(d0*inv*g[tid]     + bb[tid]);
    H[base+tid+256] = __float2half_rn(d1*inv*g[tid+256] + bb[tid+256]);
    H[base+tid+512] = __float2half_rn(d2*inv*g[tid+512] + bb[tid+512]);
}

// ---- RoPE tables ----
__global__ void rope_pre(const float* __restrict__ centers, const float* __restrict__ scales){
    int t = blockIdx.x, b = blockIdx.y, j = threadIdx.x;
    float f = expf(-4.605170185988091f*(float)(j&15)*(1.f/16.f));
    if (b < B_){
        float gy=(t/7+0.5f)*(2.f/7.f)-1.f, gx=(t%7+0.5f)*(2.f/7.f)-1.f;
        float sc=scales[b];
        float pos=(j<16)?(centers[2*b]+sc*gy):(centers[2*b+1]+sc*gx);
        if (t < NTL_){
            float a=pos*f;
            int idx=(b*NTL_+t)*32+j;
            g_lsin[idx]=sinf(a); g_lcos[idx]=cosf(a);
        }
    } else {
        float gy=(t/16+0.5f)*(2.f/16.f)-1.f, gx=(t%16+0.5f)*(2.f/16.f)-1.f;
        float pos=(j<16)?gy:gx;
        float a=pos*f;
        g_ssin[t*32+j]=sinf(a); g_scos[t*32+j]=cosf(a);
    }
}

// ---- attn4: cp.async 3-stage K/V pipeline, P overlays S ----
#define AQ4   0
#define AKV4(s) (8192 + (s)*8192)
#define AS4   32768
#define SMATT4 98304
__global__ __launch_bounds__(256,2) void attn4(
    const __half* __restrict__ Q, const __half* __restrict__ K, const __half* __restrict__ V,
    __half* __restrict__ Oh, int Nq, int Nk, int qs, int ks,
    const float* __restrict__ qS, const float* __restrict__ qC, int qpre, int qbi,
    const float* __restrict__ kS, const float* __restrict__ kC, int kpre, int kbi)
{
    extern __shared__ char smc[];
    const uint32_t sb = smem_to_u32(smc);
    float* Sm = reinterpret_cast<float*>(smc + AS4);
    const int q0 = blockIdx.x<<6, h = blockIdx.y, b = blockIdx.z;
    const int tid = threadIdx.x, wid = tid>>5, lane = tid&31;
    const int mw = wid>>1, nw = wid&1;
    const int NC = (Nk + 63) >> 6;

    auto issueK = [&](int c){
        int c0 = c<<6;
        const uint32_t sbase = sb + AKV4(c%3);
        #pragma unroll
        for (int it=0; it<2; it++){
            int u = (it<<8) + tid;
            int r = u>>3, seg = u&7;
            int t = c0 + r;
            int tr = (t < Nk) ? t : (Nk-1);
            uint32_t ss = (t < Nk) ? 16u : 0u;
            CPA16Z(sbase + SWZ((uint32_t)(r*128 + seg*16)),
                   K + (size_t)(b*Nk+tr)*ks + h*64 + (seg<<3), ss);
        }
        CPA_COMMIT();
    };
    auto issueV = [&](int c){
        int c0 = c<<6;
        const uint32_t sbase = sb + AKV4(c%3);
        #pragma unroll
        for (int it=0; it<2; it++){
            int u = (it<<8) + tid;
            int r = u>>3, seg = u&7;
            int t = c0 + r;
            int tr = (t < Nk) ? t : (Nk-1);
            uint32_t ss = (t < Nk) ? 16u : 0u;
            CPA16Z(sbase + SWZ((uint32_t)(r*128 + seg*16)),
                   V + (size_t)(b*Nk+tr)*ks + h*64 + (seg<<3), ss);
        }
        CPA_COMMIT();
    };

    issueK(0);
    if (NC>1) issueK(1);

    // Q tile load + rope (plain loads, once)
    {
        int r = tid>>2, pj = (tid&3)<<3;
        int t = q0 + r;
        uint4 lo = make_uint4(0,0,0,0), hi = make_uint4(0,0,0,0);
        if (t < Nq){
            const __half* qp = Q + (size_t)(b*Nq+t)*qs + h*64;
            lo = *reinterpret_cast<const uint4*>(qp + pj);
            hi = *reinterpret_cast<const uint4*>(qp + pj + 32);
            if (t >= qpre){
                int so = (qbi ? t*32 : (b*NTL_ + (t-qpre))*32) + pj;
                __half2* l2 = reinterpret_cast<__half2*>(&lo);
                __half2* h2 = reinterpret_cast<__half2*>(&hi);
                #pragma unroll
                for (int jj=0;jj<4;jj++){
                    float2 x1 = __half22float2(l2[jj]);
                    float2 x2 = __half22float2(h2[jj]);
                    float s0=qS[so+2*jj], c0=qC[so+2*jj];
                    float s1=qS[so+2*jj+1], c1=qC[so+2*jj+1];
                    l2[jj] = __floats2half2_rn(x1.x*c0-x2.x*s0, x1.y*c1-x2.y*s1);
                    h2[jj] = __floats2half2_rn(x2.x*c0+x1.x*s0, x2.y*c1+x1.y*s1);
                }
            }
        }
        *reinterpret_cast<uint4*>(smc + AQ4 + SWZ(r*128 + pj*2)) = lo;
        *reinterpret_cast<uint4*>(smc + AQ4 + SWZ(r*128 + pj*2 + 64)) = hi;
    }

    // QK pass
    for (int c=0;c<NC;c++){
        int G = (NC>1) ? ((c+2<NC)?(c+2):NC) : 1;
        if (G-(c+1) > 0) asm volatile("cp.async.wait_group 1;");
        else             asm volatile("cp.async.wait_group 0;");
        __syncthreads();
        if (c+2 < NC) issueK(c+2);
        const uint32_t sbase = sb + AKV4(c%3);
        {   // rope fix-up on K chunk (in smem)
            int r = tid>>2, pj = (tid&3)<<3;
            int t = (c<<6) + r;
            if (t < Nk && t >= kpre){
                uint4 lo = *reinterpret_cast<uint4*>(smc + AKV4(c%3) + SWZ(r*128 + pj*2));
                uint4 hi = *reinterpret_cast<uint4*>(smc + AKV4(c%3) + SWZ(r*128 + pj*2 + 64));
                int so = (kbi ? t*32 : (b*NTL_ + (t-kpre))*32) + pj;
                __half2* l2 = reinterpret_cast<__half2*>(&lo);
                __half2* h2 = reinterpret_cast<__half2*>(&hi);
                #pragma unroll
                for (int jj=0;jj<4;jj++){
                    float2 x1 = __half22float2(l2[jj]);
                    float2 x2 = __half22float2(h2[jj]);
                    float s0=kS[so+2*jj], c0f=kC[so+2*jj];
                    float s1=kS[so+2*jj+1], c1f=kC[so+2*jj+1];
                    l2[jj] = __floats2half2_rn(x1.x*c0f-x2.x*s0, x1.y*c1f-x2.y*s1);
                    h2[jj] = __floats2half2_rn(x2.x*c0f+x1.x*s0, x2.y*c1f+x1.y*s1);
                }
                *reinterpret_cast<uint4*>(smc + AKV4(c%3) + SWZ(r*128 + pj*2)) = lo;
                *reinterpret_cast<uint4*>(smc + AKV4(c%3) + SWZ(r*128 + pj*2 + 64)) = hi;
            }
        }
        __syncthreads();
        float acc[4][4] = {};
        #pragma unroll
        for (int ks_=0;ks_<4;ks_++){
            uint32_t af[4];
            ldsm4(af, sb + AQ4 + SWZ(((mw<<4)+(lane&15))*128 + ((ks_<<4)+((lane>>4)<<3))*2));
            #pragma unroll
            for (int np=0;np<2;np++){
                uint32_t bf[4];
                int krow = (nw<<5)+(np<<4)+(lane&7)+((lane>>4)<<3);
                ldsm4(bf, sbase + SWZ(krow*128 + ((ks_<<4)+(((lane>>3)&1)<<3))*2));
                mma16816(acc[2*np],   af, bf);
                mma16816(acc[2*np+1], af, bf+2);
            }
        }
        int g = lane>>2, tq = lane&3;
        int c0 = c<<6;
        #pragma unroll
        for (int j=0;j<4;j++){
            int col = c0 + (nw<<5) + ((j>>1)<<4) + ((j&1)<<3) + (tq<<1);
            int r0 = (mw<<4)+g;
            float* s0 = Sm + r0*256 + col;
            s0[0]=acc[j][0]*0.125f; s0[1]=acc[j][1]*0.125f;
            float* s1 = s0 + 8*256;
            s1[0]=acc[j][2]*0.125f; s1[1]=acc[j][3]*0.125f;
        }
    }
    __syncthreads();
    // prefetch V0/V1 (overlaps softmax)
    issueV(0);
    if (NC>1) issueV(1);

    // softmax: keep row in regs, write fp16 P over S region (row*1024, 512B swizzled)
    {
        int NW = NC<<1;   // 32-wide groups per row (Nkp/32)
        for (int rr=0;rr<8;rr++){
            int row = (wid<<3)+rr;
            float* Srow = Sm + row*256;
            float v[8];
            float m = -1e30f;
            for (int k2=0;k2<NW;k2++){
                int i = lane + (k2<<5);
                v[k2] = (i<Nk) ? Srow[i] : -1e30f;
                m = fmaxf(m, v[k2]);
            }
            #pragma unroll
            for (int o=16;o>0;o>>=1) m = fmaxf(m, __shfl_xor_sync(0xffffffffu, m, o));
            float sum = 0.f;
            for (int k2=0;k2<NW;k2++){
                int i = lane + (k2<<5);
                v[k2] = (i<Nk) ? expf(v[k2]-m) : 0.f;
                sum += v[k2];
            }
            #pragma unroll
            for (int o=16;o>0;o>>=1) sum += __shfl_xor_sync(0xffffffffu, sum, o);
            float inv = 1.f/sum;
            for (int k2=0;k2<NW;k2++){
                int i = lane + (k2<<5);
                *reinterpret_cast<__half*>(smc + AS4 + row*1024 +
                    (((i>>3)^(row&7))<<4) + ((i&7)<<1)) = __float2half_rn(v[k2]*inv);
            }
        }
    }
    __syncthreads();

    // PV pass
    float oacc[4][4] = {};
    for (int c=0;c<NC;c++){
        int GV = (NC>1) ? ((c+2<NC)?(c+2):NC) : 1;
        if (GV-(c+1) > 0) asm volatile("cp.async.wait_group 1;");
        else              asm volatile("cp.async.wait_group 0;");
        __syncthreads();
        if (c+2 < NC) issueV(c+2);
        const uint32_t sbase = sb + AKV4(c%3);
        int c0 = c<<6;
        #pragma unroll
        for (int ks_=0;ks_<4;ks_++){
            uint32_t af[4];
            int prow = (mw<<4)+(lane&15);
            int pcol = c0 + (ks_<<4) + ((lane>>4)<<3);
            ldsm4(af, sb + AS4 + prow*1024 + (((pcol>>3)^(prow&7))<<4));
            #pragma unroll
            for (int np=0;np<2;np++){
                uint32_t bf[4];
                int vrow = (ks_<<4) + (((lane>>3)&1)<<3) + (lane&7);
                int vcol = (nw<<5) + (np<<4) + ((lane>>4)<<3);
                ldsm4t(bf, sbase + SWZ(vrow*128 + vcol*2));
                mma16816(oacc[2*np],   af, bf);
                mma16816(oacc[2*np+1], af, bf+2);
            }
        }
        __syncthreads();
    }
    {
        int g = lane>>2, tq = lane&3;
        #pragma unroll
        for (int j=0;j<4;j++){
            int col = (nw<<5)+((j>>1)<<4)+((j&1)<<3)+(tq<<1);
            int r0 = (mw<<4)+g;
            if (q0+r0 < Nq){
                size_t i0 = (size_t)(b*Nq + q0 + r0)*D_ + h*64 + col;
                *reinterpret_cast<__half2*>(Oh+i0) = __floats2half2_rn(oacc[j][0], oacc[j][1]);
            }
            if (q0+r0+8 < Nq){
                size_t i1 = (size_t)(b*Nq + q0 + r0 + 8)*D_ + h*64 + col;
                *reinterpret_cast<__half2*>(Oh+i1) = __floats2half2_rn(oacc[j][2], oacc[j][3]);
            }
        }
    }
}

__global__ void bcast_scene(const float* __restrict__ st){
    int off = blockIdx.x*256 + threadIdx.x;
    float v = st[off];
    size_t i = (size_t)blockIdx.y*(NS_*D_) + off;
    g_scene[i] = v;
    g_sh[i] = __float2half_rn(v);
}

extern "C" void kernel_launch(void* const* d_in, const int* in_sizes, int n_in,
                              void* d_out, int out_size)
{
    (void)in_sizes; (void)n_in; (void)out_size;
    const float *in_local=(const float*)d_in[0], *in_centers=(const float*)d_in[1],
        *in_scales=(const float*)d_in[2], *in_scene=(const float*)d_in[3],
        *rgate=(const float*)d_in[4], *wgate=(const float*)d_in[5],
        *rWq=(const float*)d_in[6], *rWk=(const float*)d_in[7], *rWv=(const float*)d_in[8],
        *rWo=(const float*)d_in[9], *wWq=(const float*)d_in[10], *wWk=(const float*)d_in[11],
        *wWv=(const float*)d_in[12], *wWo=(const float*)d_in[13],
        *ln1g=(const float*)d_in[14], *ln1b=(const float*)d_in[15],
        *qkvW=(const float*)d_in[16], *aWo=(const float*)d_in[17],
        *ln2g=(const float*)d_in[18], *ln2b=(const float*)d_in[19],
        *mW1=(const float*)d_in[20], *mW2=(const float*)d_in[21];

    float *local,*scene,*lsin,*lcos,*ssin,*scos;
    __half *wt,*lh,*sh,*aoh,*hbh,*mh,*qh,*kvh,*qkvh;
    cudaGetSymbolAddress((void**)&local,g_local); cudaGetSymbolAddress((void**)&scene,g_scene);
    cudaGetSymbolAddress((void**)&lsin,g_lsin); cudaGetSymbolAddress((void**)&lcos,g_lcos);
    cudaGetSymbolAddress((void**)&ssin,g_ssin); cudaGetSymbolAddress((void**)&scos,g_scos);
    cudaGetSymbolAddress((void**)&wt,g_wt);
    cudaGetSymbolAddress((void**)&lh,g_lh);   cudaGetSymbolAddress((void**)&sh,g_sh);
    cudaGetSymbolAddress((void**)&aoh,g_aoh); cudaGetSymbolAddress((void**)&hbh,g_hbh);
    cudaGetSymbolAddress((void**)&mh,g_mh);
    cudaGetSymbolAddress((void**)&qh,g_qh);   cudaGetSymbolAddress((void**)&kvh,g_kvh);
    cudaGetSymbolAddress((void**)&qkvh,g_qkvh);

    cudaFuncSetAttribute(mmagemm<3,1>, cudaFuncAttributeMaxDynamicSharedMemorySize, SMEMG);
    cudaFuncSetAttribute(mmagemm_pair, cudaFuncAttributeMaxDynamicSharedMemorySize, SMEMG);
    cudaFuncSetAttribute(mmagemm64<3,0>, cudaFuncAttributeMaxDynamicSharedMemorySize, SMG64);
    cudaFuncSetAttribute(mmagemm64<0,2>, cudaFuncAttributeMaxDynamicSharedMemorySize, SMG64);
    cudaFuncSetAttribute(mmagemm64<2,0>, cudaFuncAttributeMaxDynamicSharedMemorySize, SMG64);
    cudaFuncSetAttribute(mmagemm64<1,2>, cudaFuncAttributeMaxDynamicSharedMemorySize, SMG64);
    cudaFuncSetAttribute(mmagemm64<2,1>, cudaFuncAttributeMaxDynamicSharedMemorySize, SMG64);
    cudaFuncSetAttribute(attn4, cudaFuncAttributeMaxDynamicSharedMemorySize, SMATT4);

    const size_t LS = 20*DD_;
    wsplit_all<<<dim3(11520,12), dim3(32,8)>>>(rWq,rWk,rWv,rWo,wWq,wWk,wWv,wWo,
                                               qkvW,aWo,mW1,mW2, wt);
    aconv<<<ML_*D_/1024,256>>>(in_local, lh);
    bcast_scene<<<dim3(NS_*D_/256, B_),256>>>(in_scene);

    for (int i=0;i<12;i++){
        const __half* wb = wt + (size_t)i*LS;
        // ---- READ cross-attn: q(local) || kv(scene) grouped ----
        mmagemm_pair<<<324+3072, 256, SMEMG>>>(lh, wb+0*DD_, qh, 768, 6, 324,
                                               sh, wb+1*DD_, kvh, 1536, 12);
        if (i==0){
            rope_pre<<<dim3(NS_,B_+1),32>>>(in_centers, in_scales);
            copyf<<<ML_*D_/1024,256>>>(in_local, local);
        }
        attn4<<<dim3(1,NH_,B_),256,SMATT4>>>(qh, kvh, kvh+768, aoh, NL_, NS_, 768, 1536,
                                             lsin,lcos,P_,0, ssin,scos,0,1);
        mmagemm64<3,0><<<dim3(6,108),  256, SMG64>>>(aoh, wb+3*DD_, local, nullptr, rgate+(size_t)i*D_, ML_, 768, 768);
        // ---- ViT block ----
        layernorm_k<<<ML_,256>>>(local, hbh, ln1g+(size_t)i*D_, ln1b+(size_t)i*D_);
        mmagemm64<0,2><<<dim3(18,108), 256, SMG64>>>(hbh, wb+8*DD_, nullptr, qkvh, nullptr, ML_, 2304, 768);
        attn4<<<dim3(1,NH_,B_),256,SMATT4>>>(qkvh, qkvh+768, qkvh+1536, aoh, NL_, NL_, 2304, 2304,
                                             lsin,lcos,P_,0, lsin,lcos,P_,0);
        mmagemm64<2,0><<<dim3(6,108),  256, SMG64>>>(aoh, wb+11*DD_, local, nullptr, nullptr, ML_, 768, 768);
        layernorm_k<<<ML_,256>>>(local, hbh, ln2g+(size_t)i*D_, ln2b+(size_t)i*D_);
        mmagemm64<1,2><<<dim3(24,108), 256, SMG64>>>(hbh, wb+12*DD_, nullptr, mh, nullptr, ML_, 3072, 768);
        mmagemm64<2,1><<<dim3(6,108),  256, SMG64>>>(mh, wb+16*DD_, local, lh, nullptr, ML_, 768, 3072);
        // ---- WRITE cross-attn: q(scene) || kv(local) grouped ----
        mmagemm_pair<<<1536+648, 256, SMEMG>>>(sh, wb+4*DD_, qh, 768, 6, 1536,
                                               lh, wb+5*DD_, kvh, 1536, 12);
        attn4<<<dim3(4,NH_,B_),256,SMATT4>>>(qh, kvh, kvh+768, aoh, NS_, NL_, 768, 1536,
                                             ssin,scos,0,1, lsin,lcos,P_,0);
        mmagemm<3,1><<<dim3(6,256),  256, SMEMG>>>(aoh, wb+7*DD_, scene, sh, wgate+(size_t)i*D_, MS_, 768, 768);
    }

    cudaMemcpyAsync(d_out, local, sizeof(float)*(size_t)ML_*D_, cudaMemcpyDeviceToDevice);
    cudaMemcpyAsync((float*)d_out + (size_t)ML_*D_, scene, sizeof(float)*(size_t)MS_*D_,
                    cudaMemcpyDeviceToDevice);
}